// round 3
// baseline (speedup 1.0000x reference)
#include <cuda_runtime.h>

// Output tuple order: (item_agg [NI,64], entity_agg [NE,64], user_agg [NU,64])
// Key simplification: softmax(...).sum(axis=1) == 1, so user/item agg = 2*(mat @ aspect_emb).

#define CH 64

__device__ float g_counts[102400];  // NE = 100000 fits
__device__ int   g_idx64;           // 1 if edge buffers are int64, 0 if int32

// Detect index dtype: int64 edge_type values are in [2, 18); int32 data read
// as int64 pairs two values -> >= 2^33. Deterministic, graph-capturable.
__global__ void detect_kernel(const unsigned long long* __restrict__ et64) {
    int is64 = 1;
    for (int i = 0; i < 16; i++) {
        unsigned long long v = et64[i];
        if (v < 2ull || v >= 18ull) { is64 = 0; break; }
    }
    g_idx64 = is64;
}

// Zero entity-sum region of d_out and the counts scratch.
__global__ void zero_kernel(float4* __restrict__ out_ent4, int n_ent) {
    int i = blockIdx.x * blockDim.x + threadIdx.x;
    int nv = n_ent * 16;  // n_ent*64 floats as float4
    if (i < nv) out_ent4[i] = make_float4(0.f, 0.f, 0.f, 0.f);
    if (i < n_ent) g_counts[i] = 0.f;
}

// One block = 16 edges, 16 threads/edge (4 channels each via float4).
__global__ void edge_kernel(const float* __restrict__ ent,
                            const void* __restrict__ eidx,
                            const void* __restrict__ etype,
                            const float* __restrict__ w,
                            float* __restrict__ out_ent, int E) {
    __shared__ int s_head[16], s_tail[16], s_rel[16];
    int tid = threadIdx.x;
    int e0 = blockIdx.x * 16;
    if (tid < 16) {
        int e = e0 + tid;
        if (e < E) {
            if (g_idx64) {
                const long long* ei = (const long long*)eidx;
                const long long* et = (const long long*)etype;
                s_head[tid] = (int)ei[e];
                s_tail[tid] = (int)ei[(size_t)E + e];
                s_rel[tid]  = (int)et[e] - 2;
            } else {
                const int* ei = (const int*)eidx;
                const int* et = (const int*)etype;
                s_head[tid] = ei[e];
                s_tail[tid] = ei[(size_t)E + e];
                s_rel[tid]  = et[e] - 2;
            }
        } else {
            s_head[tid] = -1;
        }
    }
    __syncthreads();
    int el = tid >> 4, c = tid & 15;
    int head = s_head[el];
    if (head < 0) return;
    int tail = s_tail[el], rel = s_rel[el];

    float4 v  = *(const float4*)(ent + (size_t)tail * CH + c * 4);
    float4 wv = *(const float4*)(w + rel * CH + c * 4);
    float* dst = out_ent + (size_t)head * CH + c * 4;
    atomicAdd(dst + 0, v.x * wv.x);
    atomicAdd(dst + 1, v.y * wv.y);
    atomicAdd(dst + 2, v.z * wv.z);
    atomicAdd(dst + 3, v.w * wv.w);
    if (c == 0) atomicAdd(&g_counts[head], 1.0f);
}

// entity_agg = sums / max(counts, 1)
__global__ void finalize_kernel(float4* __restrict__ out_ent4, int n_ent) {
    int i = blockIdx.x * blockDim.x + threadIdx.x;
    if (i >= n_ent * 16) return;
    float inv = 1.0f / fmaxf(g_counts[i >> 4], 1.0f);
    float4 v = out_ent4[i];
    v.x *= inv; v.y *= inv; v.z *= inv; v.w *= inv;
    out_ent4[i] = v;
}

// out[r][c] = 2 * sum_k M[r][k] * A[k][c].  Block of 256 threads handles 128 rows.
// Thread (rs = tid/16, cg = tid%16) computes rows rs+16j (j=0..7), channels 4cg..4cg+3.
__global__ void gemm2_kernel(const float4* __restrict__ M4,
                             const float4* __restrict__ A4,
                             float4* __restrict__ out4, int nrows) {
    __shared__ float4 sA[64 * 16];   // sA[k*16 + cg] = A[k][4cg..4cg+3]
    __shared__ float  sM[128 * 64];  // row-major tile

    int tid = threadIdx.x;
    for (int i = tid; i < 1024; i += 256) sA[i] = A4[i];

    int r0 = blockIdx.x * 128;
    for (int i = tid; i < 2048; i += 256) {
        int row = r0 + (i >> 4);
        float4 v = (row < nrows) ? M4[(size_t)row * 16 + (i & 15)]
                                 : make_float4(0.f, 0.f, 0.f, 0.f);
        ((float4*)sM)[i] = v;
    }
    __syncthreads();

    int cg = tid & 15, rs = tid >> 4;
    float4 acc[8];
#pragma unroll
    for (int j = 0; j < 8; j++) acc[j] = make_float4(0.f, 0.f, 0.f, 0.f);

#pragma unroll 4
    for (int k = 0; k < 64; k++) {
        float4 a = sA[k * 16 + cg];
#pragma unroll
        for (int j = 0; j < 8; j++) {
            float m = sM[(rs + 16 * j) * 64 + k];
            acc[j].x = fmaf(m, a.x, acc[j].x);
            acc[j].y = fmaf(m, a.y, acc[j].y);
            acc[j].z = fmaf(m, a.z, acc[j].z);
            acc[j].w = fmaf(m, a.w, acc[j].w);
        }
    }

#pragma unroll
    for (int j = 0; j < 8; j++) {
        int row = r0 + rs + 16 * j;
        if (row < nrows) {
            out4[(size_t)row * 16 + cg] =
                make_float4(2.f * acc[j].x, 2.f * acc[j].y,
                            2.f * acc[j].z, 2.f * acc[j].w);
        }
    }
}

extern "C" void kernel_launch(void* const* d_in, const int* in_sizes, int n_in,
                              void* d_out, int out_size) {
    const float* entity_emb = (const float*)d_in[0];
    // d_in[1] item_emb, d_in[2] user_emb: unused (softmax row-sums == 1)
    const float* aspect_emb = (const float*)d_in[3];
    const void*  edge_index = d_in[4];
    const void*  edge_type  = d_in[5];
    const float* ua         = (const float*)d_in[6];
    const float* ia         = (const float*)d_in[7];
    const float* weight     = (const float*)d_in[8];

    int n_ent   = in_sizes[0] / CH;
    int n_users = in_sizes[6] / CH;
    int n_items = in_sizes[7] / CH;
    int E       = in_sizes[5];

    float* out      = (float*)d_out;
    float* out_item = out;
    float* out_ent  = out + (size_t)n_items * CH;
    float* out_user = out_ent + (size_t)n_ent * CH;

    int nv = n_ent * 16;
    detect_kernel<<<1, 1>>>((const unsigned long long*)edge_type);
    zero_kernel<<<(nv + 255) / 256, 256>>>((float4*)out_ent, n_ent);
    edge_kernel<<<(E + 15) / 16, 256>>>(entity_emb, edge_index, edge_type,
                                        weight, out_ent, E);
    gemm2_kernel<<<(n_users + 127) / 128, 256>>>((const float4*)ua,
                                                 (const float4*)aspect_emb,
                                                 (float4*)out_user, n_users);
    gemm2_kernel<<<(n_items + 127) / 128, 256>>>((const float4*)ia,
                                                 (const float4*)aspect_emb,
                                                 (float4*)out_item, n_items);
    finalize_kernel<<<(nv + 255) / 256, 256>>>((float4*)out_ent, n_ent);
}

// round 6
// speedup vs baseline: 1.7458x; 1.7458x over previous
#include <cuda_runtime.h>

// Output tuple order: (item_agg [NI,64], entity_agg [NE,64], user_agg [NU,64])
// softmax(...).sum(axis=1) == 1  =>  user/item agg = 2*(mat @ aspect_emb).

#define CH 64

__device__ float g_counts[102400];
__device__ int   g_idx64;

#define FMA2(d, a, b, c) \
    asm("fma.rn.f32x2 %0, %1, %2, %3;" : "=l"(d) : "l"(a), "l"(b), "l"(c))

// Detect index dtype (int64 edge_type values lie in [2,18); int32 pairs don't).
__global__ void detect_kernel(const unsigned long long* __restrict__ et64) {
    int is64 = 1;
    for (int i = 0; i < 16; i++) {
        unsigned long long v = et64[i];
        if (v < 2ull || v >= 18ull) { is64 = 0; break; }
    }
    g_idx64 = is64;
}

__global__ void zero_kernel(float4* __restrict__ out_ent4, int n_ent) {
    int i = blockIdx.x * blockDim.x + threadIdx.x;
    int nv = n_ent * 16;
    if (i < nv) out_ent4[i] = make_float4(0.f, 0.f, 0.f, 0.f);
    if (i < n_ent) g_counts[i] = 0.f;
}

// 64 edges per 256-thread block; 16 threads/edge (float4 channels).
// Weights staged in smem; scatter via one red.global.add.v4.f32 per thread.
__global__ void edge_kernel(const float4* __restrict__ ent4,
                            const void* __restrict__ eidx,
                            const void* __restrict__ etype,
                            const float4* __restrict__ w4,
                            float* __restrict__ out_ent, int E) {
    __shared__ int    s_head[64], s_tail[64], s_rel[64];
    __shared__ float4 s_w[256];   // 16 relations x 16 float4

    int tid = threadIdx.x;
    s_w[tid] = w4[tid];

    int e0 = blockIdx.x * 64;
    int is64 = g_idx64;
    if (tid < 64) {
        int e = e0 + tid;
        if (e < E) {
            s_head[tid] = is64 ? (int)((const long long*)eidx)[e]
                               : ((const int*)eidx)[e];
        } else {
            s_head[tid] = -1;
        }
    } else if (tid < 128) {
        int t = tid - 64, e = e0 + t;
        if (e < E) {
            s_tail[t] = is64 ? (int)((const long long*)eidx)[(size_t)E + e]
                             : ((const int*)eidx)[(size_t)E + e];
        }
    } else if (tid < 192) {
        int t = tid - 128, e = e0 + t;
        if (e < E) {
            s_rel[t] = (is64 ? (int)((const long long*)etype)[e]
                             : ((const int*)etype)[e]) - 2;
        }
    }
    __syncthreads();

    int c = tid & 15;
    int eb = tid >> 4;
#pragma unroll
    for (int it = 0; it < 4; it++) {
        int el = it * 16 + eb;
        int head = s_head[el];
        if (head < 0) continue;
        float4 v  = ent4[(size_t)s_tail[el] * 16 + c];
        float4 wv = s_w[s_rel[el] * 16 + c];
        float rx = v.x * wv.x, ry = v.y * wv.y;
        float rz = v.z * wv.z, rw = v.w * wv.w;
        float* dst = out_ent + (size_t)head * CH + c * 4;
        asm volatile("red.global.add.v4.f32 [%0], {%1,%2,%3,%4};"
                     :: "l"(dst), "f"(rx), "f"(ry), "f"(rz), "f"(rw)
                     : "memory");
        if (c == 0) atomicAdd(&g_counts[head], 1.0f);
    }
}

__global__ void finalize_kernel(float4* __restrict__ out_ent4, int n_ent) {
    int i = blockIdx.x * blockDim.x + threadIdx.x;
    if (i >= n_ent * 16) return;
    float inv = 1.0f / fmaxf(g_counts[i >> 4], 1.0f);
    float4 v = out_ent4[i];
    v.x *= inv; v.y *= inv; v.z *= inv; v.w *= inv;
    out_ent4[i] = v;
}

// out[r][c] = 2 * sum_k M[r][k] * A[k][c] using packed fma.rn.f32x2.
// 256 threads, 64-row tile. rs = tid>>4 handles rows rs*4..rs*4+3;
// cg = tid&15 handles channels 4cg..4cg+3 (two f32x2 pairs).
// sM2 holds each M element pre-duplicated as (m,m) so m2 is one LDS.64;
// sA's channel pairs are naturally adjacent (ulonglong2 view).
__global__ void gemm2_kernel(const float4* __restrict__ M4,
                             const float4* __restrict__ A4,
                             float4* __restrict__ out4, int nrows) {
    __shared__ float4 sA[64 * 16];          // 16KB: sA[k*16+cg] = A[k][4cg..]
    __shared__ float2 sM2[64 * 64];         // 32KB: sM2[row*64+k] = (m, m)

    int tid = threadIdx.x;
    for (int i = tid; i < 1024; i += 256) sA[i] = A4[i];

    int r0 = blockIdx.x * 64;
    for (int i = tid; i < 1024; i += 256) {
        int row = i >> 4, c4 = i & 15;
        float4 v = (r0 + row < nrows) ? M4[(size_t)(r0 + row) * 16 + c4]
                                      : make_float4(0.f, 0.f, 0.f, 0.f);
        float2* p = &sM2[row * 64 + c4 * 4];
        p[0] = make_float2(v.x, v.x);
        p[1] = make_float2(v.y, v.y);
        p[2] = make_float2(v.z, v.z);
        p[3] = make_float2(v.w, v.w);
    }
    __syncthreads();

    int cg = tid & 15, rs = tid >> 4;
    unsigned long long accLo[4] = {0ull, 0ull, 0ull, 0ull};
    unsigned long long accHi[4] = {0ull, 0ull, 0ull, 0ull};

#pragma unroll 4
    for (int k = 0; k < 64; k++) {
        ulonglong2 a = *(const ulonglong2*)&sA[k * 16 + cg];
#pragma unroll
        for (int j = 0; j < 4; j++) {
            unsigned long long m2 =
                *(const unsigned long long*)&sM2[(rs * 4 + j) * 64 + k];
            FMA2(accLo[j], m2, a.x, accLo[j]);
            FMA2(accHi[j], m2, a.y, accHi[j]);
        }
    }

#pragma unroll
    for (int j = 0; j < 4; j++) {
        int row = r0 + rs * 4 + j;
        if (row < nrows) {
            float2 lo = *(float2*)&accLo[j];
            float2 hi = *(float2*)&accHi[j];
            out4[(size_t)row * 16 + cg] =
                make_float4(2.f * lo.x, 2.f * lo.y, 2.f * hi.x, 2.f * hi.y);
        }
    }
}

extern "C" void kernel_launch(void* const* d_in, const int* in_sizes, int n_in,
                              void* d_out, int out_size) {
    const float* entity_emb = (const float*)d_in[0];
    const float* aspect_emb = (const float*)d_in[3];
    const void*  edge_index = d_in[4];
    const void*  edge_type  = d_in[5];
    const float* ua         = (const float*)d_in[6];
    const float* ia         = (const float*)d_in[7];
    const float* weight     = (const float*)d_in[8];

    int n_ent   = in_sizes[0] / CH;
    int n_users = in_sizes[6] / CH;
    int n_items = in_sizes[7] / CH;
    int E       = in_sizes[5];

    float* out      = (float*)d_out;
    float* out_item = out;
    float* out_ent  = out + (size_t)n_items * CH;
    float* out_user = out_ent + (size_t)n_ent * CH;

    int nv = n_ent * 16;
    detect_kernel<<<1, 1>>>((const unsigned long long*)edge_type);
    zero_kernel<<<(nv + 255) / 256, 256>>>((float4*)out_ent, n_ent);
    edge_kernel<<<(E + 63) / 64, 256>>>((const float4*)entity_emb, edge_index,
                                        edge_type, (const float4*)weight,
                                        out_ent, E);
    gemm2_kernel<<<(n_users + 63) / 64, 256>>>((const float4*)ua,
                                               (const float4*)aspect_emb,
                                               (float4*)out_user, n_users);
    gemm2_kernel<<<(n_items + 63) / 64, 256>>>((const float4*)ia,
                                               (const float4*)aspect_emb,
                                               (float4*)out_item, n_items);
    finalize_kernel<<<(nv + 255) / 256, 256>>>((float4*)out_ent, n_ent);
}

// round 7
// speedup vs baseline: 1.7462x; 1.0002x over previous
#include <cuda_runtime.h>

// Output tuple order: (item_agg [NI,64], entity_agg [NE,64], user_agg [NU,64])
// softmax(...).sum(axis=1) == 1  =>  user/item agg = 2*(mat @ aspect_emb).

#define CH 64

__device__ float g_counts[102400];
__device__ int   g_idx64;

#define FMA2(d, a, b, c) \
    asm("fma.rn.f32x2 %0, %1, %2, %3;" : "=l"(d) : "l"(a), "l"(b), "l"(c))

// Detect index dtype (int64 edge_type values lie in [2,18); int32 pairs don't).
__global__ void detect_kernel(const unsigned long long* __restrict__ et64) {
    int is64 = 1;
    for (int i = 0; i < 16; i++) {
        unsigned long long v = et64[i];
        if (v < 2ull || v >= 18ull) { is64 = 0; break; }
    }
    g_idx64 = is64;
}

__global__ void zero_kernel(float4* __restrict__ out_ent4, int n_ent) {
    int i = blockIdx.x * blockDim.x + threadIdx.x;
    int nv = n_ent * 16;
    if (i < nv) out_ent4[i] = make_float4(0.f, 0.f, 0.f, 0.f);
    if (i < n_ent) g_counts[i] = 0.f;
}

// 64 edges per 256-thread block; 16 threads/edge (float4 channels).
// Weights staged in smem; scatter via one red.global.add.v4.f32 per thread.
__global__ void edge_kernel(const float4* __restrict__ ent4,
                            const void* __restrict__ eidx,
                            const void* __restrict__ etype,
                            const float4* __restrict__ w4,
                            float* __restrict__ out_ent, int E) {
    __shared__ int    s_head[64], s_tail[64], s_rel[64];
    __shared__ float4 s_w[256];   // 16 relations x 16 float4

    int tid = threadIdx.x;
    s_w[tid] = w4[tid];

    int e0 = blockIdx.x * 64;
    int is64 = g_idx64;
    if (tid < 64) {
        int e = e0 + tid;
        if (e < E) {
            s_head[tid] = is64 ? (int)((const long long*)eidx)[e]
                               : ((const int*)eidx)[e];
        } else {
            s_head[tid] = -1;
        }
    } else if (tid < 128) {
        int t = tid - 64, e = e0 + t;
        if (e < E) {
            s_tail[t] = is64 ? (int)((const long long*)eidx)[(size_t)E + e]
                             : ((const int*)eidx)[(size_t)E + e];
        }
    } else if (tid < 192) {
        int t = tid - 128, e = e0 + t;
        if (e < E) {
            s_rel[t] = (is64 ? (int)((const long long*)etype)[e]
                             : ((const int*)etype)[e]) - 2;
        }
    }
    __syncthreads();

    int c = tid & 15;
    int eb = tid >> 4;
#pragma unroll
    for (int it = 0; it < 4; it++) {
        int el = it * 16 + eb;
        int head = s_head[el];
        if (head < 0) continue;
        float4 v  = ent4[(size_t)s_tail[el] * 16 + c];
        float4 wv = s_w[s_rel[el] * 16 + c];
        float rx = v.x * wv.x, ry = v.y * wv.y;
        float rz = v.z * wv.z, rw = v.w * wv.w;
        float* dst = out_ent + (size_t)head * CH + c * 4;
        asm volatile("red.global.add.v4.f32 [%0], {%1,%2,%3,%4};"
                     :: "l"(dst), "f"(rx), "f"(ry), "f"(rz), "f"(rw)
                     : "memory");
        if (c == 0) atomicAdd(&g_counts[head], 1.0f);
    }
}

__global__ void finalize_kernel(float4* __restrict__ out_ent4, int n_ent) {
    int i = blockIdx.x * blockDim.x + threadIdx.x;
    if (i >= n_ent * 16) return;
    float inv = 1.0f / fmaxf(g_counts[i >> 4], 1.0f);
    float4 v = out_ent4[i];
    v.x *= inv; v.y *= inv; v.z *= inv; v.w *= inv;
    out_ent4[i] = v;
}

// out[r][c] = 2 * sum_k M[r][k] * A[k][c] with packed fma.rn.f32x2.
// 256 threads, 64-row tile. rs = tid>>4 owns rows rs*4..rs*4+3; cg = tid&15
// owns channels 4cg..4cg+3. M tile stored duplicated in float4 pairs:
// sM4[row*32 + t] = (m_{2t}, m_{2t}, m_{2t+1}, m_{2t+1}) so ONE broadcast
// LDS.128 feeds 4 FMA2s (amortizes the 1-wavefront minimum per LDS).
__global__ void gemm2_kernel(const float4* __restrict__ M4,
                             const float4* __restrict__ A4,
                             float4* __restrict__ out4, int nrows) {
    __shared__ float4 sA[64 * 16];   // 16KB: sA[k*16+cg] = A[k][4cg..4cg+3]
    __shared__ float4 sM4[64 * 32];  // 32KB: duplicated k-pairs per row

    int tid = threadIdx.x;
    for (int i = tid; i < 1024; i += 256) sA[i] = A4[i];

    int r0 = blockIdx.x * 64;
    for (int i = tid; i < 1024; i += 256) {
        int row = i >> 4, c4 = i & 15;
        float4 v = (r0 + row < nrows) ? M4[(size_t)(r0 + row) * 16 + c4]
                                      : make_float4(0.f, 0.f, 0.f, 0.f);
        sM4[row * 32 + c4 * 2]     = make_float4(v.x, v.x, v.y, v.y);
        sM4[row * 32 + c4 * 2 + 1] = make_float4(v.z, v.z, v.w, v.w);
    }
    __syncthreads();

    int cg = tid & 15, rs = tid >> 4;
    unsigned long long accLo[4] = {0ull, 0ull, 0ull, 0ull};
    unsigned long long accHi[4] = {0ull, 0ull, 0ull, 0ull};

#pragma unroll 8
    for (int t = 0; t < 32; t++) {
        ulonglong2 a0 = *(const ulonglong2*)&sA[(2 * t) * 16 + cg];
        ulonglong2 a1 = *(const ulonglong2*)&sA[(2 * t + 1) * 16 + cg];
#pragma unroll
        for (int j = 0; j < 4; j++) {
            ulonglong2 mm = *(const ulonglong2*)&sM4[(rs * 4 + j) * 32 + t];
            FMA2(accLo[j], mm.x, a0.x, accLo[j]);   // mm.x = (m_2t, m_2t)
            FMA2(accHi[j], mm.x, a0.y, accHi[j]);
            FMA2(accLo[j], mm.y, a1.x, accLo[j]);   // mm.y = (m_2t+1, m_2t+1)
            FMA2(accHi[j], mm.y, a1.y, accHi[j]);
        }
    }

#pragma unroll
    for (int j = 0; j < 4; j++) {
        int row = r0 + rs * 4 + j;
        if (row < nrows) {
            float2 lo = *(float2*)&accLo[j];
            float2 hi = *(float2*)&accHi[j];
            out4[(size_t)row * 16 + cg] =
                make_float4(2.f * lo.x, 2.f * lo.y, 2.f * hi.x, 2.f * hi.y);
        }
    }
}

extern "C" void kernel_launch(void* const* d_in, const int* in_sizes, int n_in,
                              void* d_out, int out_size) {
    const float* entity_emb = (const float*)d_in[0];
    const float* aspect_emb = (const float*)d_in[3];
    const void*  edge_index = d_in[4];
    const void*  edge_type  = d_in[5];
    const float* ua         = (const float*)d_in[6];
    const float* ia         = (const float*)d_in[7];
    const float* weight     = (const float*)d_in[8];

    int n_ent   = in_sizes[0] / CH;
    int n_users = in_sizes[6] / CH;
    int n_items = in_sizes[7] / CH;
    int E       = in_sizes[5];

    float* out      = (float*)d_out;
    float* out_item = out;
    float* out_ent  = out + (size_t)n_items * CH;
    float* out_user = out_ent + (size_t)n_ent * CH;

    int nv = n_ent * 16;
    detect_kernel<<<1, 1>>>((const unsigned long long*)edge_type);
    zero_kernel<<<(nv + 255) / 256, 256>>>((float4*)out_ent, n_ent);
    edge_kernel<<<(E + 63) / 64, 256>>>((const float4*)entity_emb, edge_index,
                                        edge_type, (const float4*)weight,
                                        out_ent, E);
    gemm2_kernel<<<(n_users + 63) / 64, 256>>>((const float4*)ua,
                                               (const float4*)aspect_emb,
                                               (float4*)out_user, n_users);
    gemm2_kernel<<<(n_items + 63) / 64, 256>>>((const float4*)ia,
                                               (const float4*)aspect_emb,
                                               (float4*)out_item, n_items);
    finalize_kernel<<<(nv + 255) / 256, 256>>>((float4*)out_ent, n_ent);
}

// round 8
// speedup vs baseline: 2.1981x; 1.2588x over previous
#include <cuda_runtime.h>

// Output tuple order: (item_agg [NI,64], entity_agg [NE,64], user_agg [NU,64])
// softmax(...).sum(axis=1) == 1  =>  user/item agg = 2*(mat @ aspect_emb).

#define CH 64

__device__ float g_counts[102400];
__device__ int   g_idx64;

#define FMA2(d, a, b, c) \
    asm("fma.rn.f32x2 %0, %1, %2, %3;" : "=l"(d) : "l"(a), "l"(b), "l"(c))
#define DUP2(d, s) \
    asm("mov.b64 %0, {%1, %1};" : "=l"(d) : "r"(s))

// Zero entity sums + counts; thread 0 also detects index dtype
// (int64 edge_type values lie in [2,18); int32 pairs read as u64 don't).
__global__ void zero_kernel(float4* __restrict__ out_ent4, int n_ent,
                            const unsigned long long* __restrict__ et64) {
    int i = blockIdx.x * blockDim.x + threadIdx.x;
    if (i == 0) {
        int is64 = 1;
        for (int j = 0; j < 16; j++) {
            unsigned long long v = et64[j];
            if (v < 2ull || v >= 18ull) { is64 = 0; break; }
        }
        g_idx64 = is64;
    }
    int nv = n_ent * 16;
    if (i < nv) out_ent4[i] = make_float4(0.f, 0.f, 0.f, 0.f);
    if (i < n_ent) g_counts[i] = 0.f;
}

// 64 edges per 256-thread block; 16 threads/edge (float4 channels).
// Weights staged in smem; scatter via one red.global.add.v4.f32 per thread.
__global__ void edge_kernel(const float4* __restrict__ ent4,
                            const void* __restrict__ eidx,
                            const void* __restrict__ etype,
                            const float4* __restrict__ w4,
                            float* __restrict__ out_ent, int E) {
    __shared__ int    s_head[64], s_tail[64], s_rel[64];
    __shared__ float4 s_w[256];

    int tid = threadIdx.x;
    s_w[tid] = w4[tid];

    int e0 = blockIdx.x * 64;
    int is64 = g_idx64;
    if (tid < 64) {
        int e = e0 + tid;
        if (e < E) {
            s_head[tid] = is64 ? (int)((const long long*)eidx)[e]
                               : ((const int*)eidx)[e];
        } else {
            s_head[tid] = -1;
        }
    } else if (tid < 128) {
        int t = tid - 64, e = e0 + t;
        if (e < E) {
            s_tail[t] = is64 ? (int)((const long long*)eidx)[(size_t)E + e]
                             : ((const int*)eidx)[(size_t)E + e];
        }
    } else if (tid < 192) {
        int t = tid - 128, e = e0 + t;
        if (e < E) {
            s_rel[t] = (is64 ? (int)((const long long*)etype)[e]
                             : ((const int*)etype)[e]) - 2;
        }
    }
    __syncthreads();

    int c = tid & 15;
    int eb = tid >> 4;
#pragma unroll
    for (int it = 0; it < 4; it++) {
        int el = it * 16 + eb;
        int head = s_head[el];
        if (head < 0) continue;
        float4 v  = ent4[(size_t)s_tail[el] * 16 + c];
        float4 wv = s_w[s_rel[el] * 16 + c];
        float rx = v.x * wv.x, ry = v.y * wv.y;
        float rz = v.z * wv.z, rw = v.w * wv.w;
        float* dst = out_ent + (size_t)head * CH + c * 4;
        asm volatile("red.global.add.v4.f32 [%0], {%1,%2,%3,%4};"
                     :: "l"(dst), "f"(rx), "f"(ry), "f"(rz), "f"(rw)
                     : "memory");
        if (c == 0) atomicAdd(&g_counts[head], 1.0f);
    }
}

__global__ void finalize_kernel(float4* __restrict__ out_ent4, int n_ent) {
    int i = blockIdx.x * blockDim.x + threadIdx.x;
    if (i >= n_ent * 16) return;
    float inv = 1.0f / fmaxf(g_counts[i >> 4], 1.0f);
    float4 v = out_ent4[i];
    v.x *= inv; v.y *= inv; v.z *= inv; v.w *= inv;
    out_ent4[i] = v;
}

// out[r][c] = 2 * sum_k M[r][k] * A[k][c], register-blocked:
// 128 threads/block, 128-row tile. Thread (rg = tid>>3, cg = tid&7) owns
// rows rg*8..+7 and channels cg*8..+7 (32 f32x2 accumulators).
// Per k: 4 LDS.128 (2 from A row-major, 2 from M transposed) + 32 FMA2.
__global__ void __launch_bounds__(128, 4)
gemm3_kernel(const float4* __restrict__ M4, const float4* __restrict__ A4,
             float4* __restrict__ out4, int nrows) {
    __shared__ float sA[64 * 64];     // [k*64 + c]
    __shared__ float sMt[64 * 132];   // [k*132 + r], padded stride

    int tid = threadIdx.x;
    int r0 = blockIdx.x * 128;

    // Stage A (row-major [k][c] is exactly the global layout).
    for (int i = tid; i < 1024; i += 128)
        ((float4*)sA)[i] = A4[i];

    // Stage M transposed: 512 tasks (32 rowquads x 16 kquads), 4 per thread.
    // Warp lanes span 8 rq x 4 kq -> decent LDG locality + spread STS banks.
#pragma unroll
    for (int t = 0; t < 4; t++) {
        int task = tid + t * 128;
        int rq = (task >> 2) & 31;
        int kq = (task & 3) | ((task >> 7) << 2);
        float4 r[4];
#pragma unroll
        for (int i = 0; i < 4; i++) {
            int row = r0 + rq * 4 + i;
            r[i] = (row < nrows) ? M4[(size_t)row * 16 + kq]
                                 : make_float4(0.f, 0.f, 0.f, 0.f);
        }
        int kb = kq * 4;
        *(float4*)&sMt[(kb + 0) * 132 + rq * 4] = make_float4(r[0].x, r[1].x, r[2].x, r[3].x);
        *(float4*)&sMt[(kb + 1) * 132 + rq * 4] = make_float4(r[0].y, r[1].y, r[2].y, r[3].y);
        *(float4*)&sMt[(kb + 2) * 132 + rq * 4] = make_float4(r[0].z, r[1].z, r[2].z, r[3].z);
        *(float4*)&sMt[(kb + 3) * 132 + rq * 4] = make_float4(r[0].w, r[1].w, r[2].w, r[3].w);
    }
    __syncthreads();

    int cg = tid & 7, rg = tid >> 3;
    const float* pA = sA + cg * 8;
    const float* pM = sMt + rg * 8;

    unsigned long long acc[32];
#pragma unroll
    for (int i = 0; i < 32; i++) acc[i] = 0ull;

#pragma unroll 4
    for (int k = 0; k < 64; k++) {
        ulonglong2 aLo = *(const ulonglong2*)(pA + k * 64);      // ch pairs 01,23
        ulonglong2 aHi = *(const ulonglong2*)(pA + k * 64 + 4);  // ch pairs 45,67
        uint4 mA = *(const uint4*)(pM + k * 132);                // rows 0..3
        uint4 mB = *(const uint4*)(pM + k * 132 + 4);            // rows 4..7
        unsigned int mv[8] = {mA.x, mA.y, mA.z, mA.w, mB.x, mB.y, mB.z, mB.w};
#pragma unroll
        for (int j = 0; j < 8; j++) {
            unsigned long long m2; DUP2(m2, mv[j]);
            FMA2(acc[j * 4 + 0], m2, aLo.x, acc[j * 4 + 0]);
            FMA2(acc[j * 4 + 1], m2, aLo.y, acc[j * 4 + 1]);
            FMA2(acc[j * 4 + 2], m2, aHi.x, acc[j * 4 + 2]);
            FMA2(acc[j * 4 + 3], m2, aHi.y, acc[j * 4 + 3]);
        }
    }

#pragma unroll
    for (int j = 0; j < 8; j++) {
        int row = r0 + rg * 8 + j;
        if (row < nrows) {
            float2 p0 = *(float2*)&acc[j * 4 + 0];
            float2 p1 = *(float2*)&acc[j * 4 + 1];
            float2 p2 = *(float2*)&acc[j * 4 + 2];
            float2 p3 = *(float2*)&acc[j * 4 + 3];
            float4* o = &out4[(size_t)row * 16 + cg * 2];
            o[0] = make_float4(2.f * p0.x, 2.f * p0.y, 2.f * p1.x, 2.f * p1.y);
            o[1] = make_float4(2.f * p2.x, 2.f * p2.y, 2.f * p3.x, 2.f * p3.y);
        }
    }
}

extern "C" void kernel_launch(void* const* d_in, const int* in_sizes, int n_in,
                              void* d_out, int out_size) {
    const float* entity_emb = (const float*)d_in[0];
    const float* aspect_emb = (const float*)d_in[3];
    const void*  edge_index = d_in[4];
    const void*  edge_type  = d_in[5];
    const float* ua         = (const float*)d_in[6];
    const float* ia         = (const float*)d_in[7];
    const float* weight     = (const float*)d_in[8];

    int n_ent   = in_sizes[0] / CH;
    int n_users = in_sizes[6] / CH;
    int n_items = in_sizes[7] / CH;
    int E       = in_sizes[5];

    float* out      = (float*)d_out;
    float* out_item = out;
    float* out_ent  = out + (size_t)n_items * CH;
    float* out_user = out_ent + (size_t)n_ent * CH;

    // Side stream + fork/join events (created once, outside any capture).
    static cudaStream_t s1 = nullptr;
    static cudaEvent_t  ev_fork = nullptr, ev_join = nullptr;
    if (!s1) {
        cudaStreamCreateWithFlags(&s1, cudaStreamNonBlocking);
        cudaEventCreateWithFlags(&ev_fork, cudaEventDisableTiming);
        cudaEventCreateWithFlags(&ev_join, cudaEventDisableTiming);
    }

    int nv = n_ent * 16;

    // Fork: gemms are independent of the edge pipeline (disjoint outputs).
    cudaEventRecord(ev_fork, 0);
    cudaStreamWaitEvent(s1, ev_fork, 0);

    // Main stream: zero(+detect) -> edge -> finalize  (L2/atomic-bound).
    zero_kernel<<<(nv + 255) / 256, 256>>>((float4*)out_ent, n_ent,
                                           (const unsigned long long*)edge_type);
    edge_kernel<<<(E + 63) / 64, 256>>>((const float4*)entity_emb, edge_index,
                                        edge_type, (const float4*)weight,
                                        out_ent, E);
    finalize_kernel<<<(nv + 255) / 256, 256>>>((float4*)out_ent, n_ent);

    // Side stream: both gemms (FMA-bound), overlapping the edge kernel.
    gemm3_kernel<<<(n_users + 127) / 128, 128, 0, s1>>>(
        (const float4*)ua, (const float4*)aspect_emb, (float4*)out_user, n_users);
    gemm3_kernel<<<(n_items + 127) / 128, 128, 0, s1>>>(
        (const float4*)ia, (const float4*)aspect_emb, (float4*)out_item, n_items);
    cudaEventRecord(ev_join, s1);
    cudaStreamWaitEvent(0, ev_join, 0);
}